// round 7
// baseline (speedup 1.0000x reference)
#include <cuda_runtime.h>

#define NNODES 50000
#define NEDGES 800000
#define SCAN_T 1024

typedef unsigned long long u64;

__device__ __forceinline__ u64 fma2(u64 a, u64 b, u64 c) {
    u64 d;
    asm("fma.rn.f32x2 %0, %1, %2, %3;" : "=l"(d) : "l"(a), "l"(b), "l"(c));
    return d;
}

union F4U2 {
    float4 f4;
    ulonglong2 u2;
};

// ---- device-global scratch (allocation-free) ----
__device__ __align__(16) int   g_deg[NNODES];
__device__ __align__(16) int   g_rowptr[NNODES + 1];
__device__ __align__(16) int   g_cursor[NNODES];
__device__ __align__(16) int   g_csr_src[NEDGES];
__device__ __align__(16) float g_inv[NNODES];        // 1/max(deg,1)
__device__ __align__(16) float g_z[NNODES * 256];    // [z_l | z_r] stacked
__device__ __align__(16) float g_h1[NNODES * 128];
__device__ __align__(16) float g_h2[NNODES * 64];

// SEL: 0 = kernel parameter, 1 = g_h1, 2 = g_h2 (resolved in device code)
template <int SEL>
__device__ __forceinline__ const float* select_src(const float* p) {
    if (SEL == 1) return g_h1;
    if (SEL == 2) return g_h2;
    return p;
}
template <int SEL>
__device__ __forceinline__ float* select_dst(float* p) {
    if (SEL == 1) return g_h1;
    if (SEL == 2) return g_h2;
    return p;
}

// ---- CSR build (once; edge_index constant across layers) ----
__global__ void zero_deg_kernel() {
    int i = blockIdx.x * blockDim.x + threadIdx.x;
    if (i < NNODES) g_deg[i] = 0;
}

__global__ void count_kernel(const int* __restrict__ ei) {
    int e = blockIdx.x * blockDim.x + threadIdx.x;
    if (e < NEDGES) atomicAdd(&g_deg[ei[NEDGES + e]], 1);
}

__global__ void scan_kernel() {
    __shared__ int partial[SCAN_T];
    const int t = threadIdx.x;
    const int CH = (NNODES + SCAN_T - 1) / SCAN_T;
    const int base = t * CH;

    int s = 0;
    for (int i = 0; i < CH; i++) {
        int idx = base + i;
        if (idx < NNODES) s += g_deg[idx];
    }
    partial[t] = s;
    __syncthreads();
    for (int off = 1; off < SCAN_T; off <<= 1) {
        int add = (t >= off) ? partial[t - off] : 0;
        __syncthreads();
        partial[t] += add;
        __syncthreads();
    }
    int run = (t == 0) ? 0 : partial[t - 1];
    for (int i = 0; i < CH; i++) {
        int idx = base + i;
        if (idx < NNODES) {
            g_rowptr[idx] = run;
            g_cursor[idx] = run;
            g_inv[idx] = 1.0f / fmaxf((float)g_deg[idx], 1.0f);
            run += g_deg[idx];
        }
    }
    if (t == SCAN_T - 1) g_rowptr[NNODES] = partial[SCAN_T - 1];
}

__global__ void fill_kernel(const int* __restrict__ ei) {
    int e = blockIdx.x * blockDim.x + threadIdx.x;
    if (e < NEDGES) {
        int dst = ei[NEDGES + e];
        int slot = atomicAdd(&g_cursor[dst], 1);
        g_csr_src[slot] = ei[e];
    }
}

// ---- FFMA2 SGEMM: z[n][j] = x[n] . W[j], W = [Wl;Wr] (BN = 2*O rows) ----
// BM=128, BK=16, BN in {128,256}. threads = BN. Thread tile 8m x 16n,
// accumulated as packed f32x2 pairs. A stored DUPLICATED in smem so LDS.128
// yields (a,a) broadcast pairs; B LDS.128 reinterprets as (b0,b1),(b2,b3).
template <int I, int BN, int SRCSEL>
__global__ __launch_bounds__(BN, (BN == 128) ? 2 : 1)
void gemm2_kernel(const float* __restrict__ xp,
                  const float* __restrict__ Wl,
                  const float* __restrict__ Wr) {
    constexpr int BM = 128, BK = 16, O = BN / 2;
    __shared__ __align__(16) float asd[BK][2 * BM + 8];
    __shared__ __align__(16) float bs[BK][BN + 8];
    const float* x = select_src<SRCSEL>(xp);

    const int t  = threadIdx.x;
    const int m0 = blockIdx.x * BM;
    const int tm = t & 15;   // m block: tm*8
    const int tn = t >> 4;   // n block: tn*16

    __align__(16) u64 acc[8][8];
#pragma unroll
    for (int i = 0; i < 8; i++)
#pragma unroll
        for (int j = 0; j < 8; j++) acc[i][j] = 0ULL;

    for (int k0 = 0; k0 < I; k0 += BK) {
        // A tile: 128 rows x 16 k, duplicate-stored
#pragma unroll
        for (int r = 0; r < 512 / BN; r++) {
            int f   = t + r * BN;       // 0..511
            int row = f >> 2;
            int kq  = (f & 3) * 4;
            int node = m0 + row;
            float4 av = make_float4(0.f, 0.f, 0.f, 0.f);
            if (node < NNODES)
                av = *reinterpret_cast<const float4*>(x + (size_t)node * I + k0 + kq);
            asd[kq + 0][2 * row] = av.x;  asd[kq + 0][2 * row + 1] = av.x;
            asd[kq + 1][2 * row] = av.y;  asd[kq + 1][2 * row + 1] = av.y;
            asd[kq + 2][2 * row] = av.z;  asd[kq + 2][2 * row + 1] = av.z;
            asd[kq + 3][2 * row] = av.w;  asd[kq + 3][2 * row + 1] = av.w;
        }
        // B tile: BN rows x 16 k
#pragma unroll
        for (int r = 0; r < 4; r++) {
            int f  = t + r * BN;        // 0..4*BN-1
            int j  = f >> 2;
            int kq = (f & 3) * 4;
            const float* wrow = (j < O) ? (Wl + (size_t)j * I)
                                        : (Wr + (size_t)(j - O) * I);
            float4 bv = *reinterpret_cast<const float4*>(wrow + k0 + kq);
            bs[kq + 0][j] = bv.x;
            bs[kq + 1][j] = bv.y;
            bs[kq + 2][j] = bv.z;
            bs[kq + 3][j] = bv.w;
        }
        __syncthreads();
#pragma unroll
        for (int k = 0; k < BK; k++) {
            F4U2 a0, a1, a2, a3, b0, b1, b2, b3;
            const float* ar = &asd[k][16 * tm];
            a0.f4 = *reinterpret_cast<const float4*>(ar + 0);
            a1.f4 = *reinterpret_cast<const float4*>(ar + 4);
            a2.f4 = *reinterpret_cast<const float4*>(ar + 8);
            a3.f4 = *reinterpret_cast<const float4*>(ar + 12);
            const float* br = &bs[k][16 * tn];
            b0.f4 = *reinterpret_cast<const float4*>(br + 0);
            b1.f4 = *reinterpret_cast<const float4*>(br + 4);
            b2.f4 = *reinterpret_cast<const float4*>(br + 8);
            b3.f4 = *reinterpret_cast<const float4*>(br + 12);
            u64 ad[8] = {a0.u2.x, a0.u2.y, a1.u2.x, a1.u2.y,
                         a2.u2.x, a2.u2.y, a3.u2.x, a3.u2.y};
            u64 bp[8] = {b0.u2.x, b0.u2.y, b1.u2.x, b1.u2.y,
                         b2.u2.x, b2.u2.y, b3.u2.x, b3.u2.y};
#pragma unroll
            for (int mm = 0; mm < 8; mm++)
#pragma unroll
                for (int np = 0; np < 8; np++)
                    acc[mm][np] = fma2(ad[mm], bp[np], acc[mm][np]);
        }
        __syncthreads();
    }

#pragma unroll
    for (int mm = 0; mm < 8; mm++) {
        int node = m0 + tm * 8 + mm;
        if (node < NNODES) {
            float* zr = g_z + (size_t)node * BN + tn * 16;
            const float4* av = reinterpret_cast<const float4*>(&acc[mm][0]);
            *reinterpret_cast<float4*>(zr + 0)  = av[0];
            *reinterpret_cast<float4*>(zr + 4)  = av[1];
            *reinterpret_cast<float4*>(zr + 8)  = av[2];
            *reinterpret_cast<float4*>(zr + 12) = av[3];
        }
    }
}

// ---- gather-add: h[n] = inv[n] * sum_{s in N(n)} z_l[s] + z_r[n] + b ----
template <int O, int DSTSEL>
__global__ void gather_add_kernel(const float* __restrict__ b,
                                  float* __restrict__ outp) {
    float* out = select_dst<DSTSEL>(outp);
    int warp = (blockIdx.x * blockDim.x + threadIdx.x) >> 5;
    int lane = threadIdx.x & 31;
    if (warp >= NNODES) return;
    int beg = g_rowptr[warp];
    int end = g_rowptr[warp + 1];
    float inv = g_inv[warp];
    constexpr int RS = 2 * O;

    if (O == 128) {
        float4 acc = make_float4(0.f, 0.f, 0.f, 0.f);
        int j = beg;
        for (; j + 3 < end; j += 4) {
            int s0 = g_csr_src[j], s1 = g_csr_src[j + 1];
            int s2 = g_csr_src[j + 2], s3 = g_csr_src[j + 3];
            float4 v0 = reinterpret_cast<const float4*>(g_z + (size_t)s0 * RS)[lane];
            float4 v1 = reinterpret_cast<const float4*>(g_z + (size_t)s1 * RS)[lane];
            float4 v2 = reinterpret_cast<const float4*>(g_z + (size_t)s2 * RS)[lane];
            float4 v3 = reinterpret_cast<const float4*>(g_z + (size_t)s3 * RS)[lane];
            acc.x += (v0.x + v1.x) + (v2.x + v3.x);
            acc.y += (v0.y + v1.y) + (v2.y + v3.y);
            acc.z += (v0.z + v1.z) + (v2.z + v3.z);
            acc.w += (v0.w + v1.w) + (v2.w + v3.w);
        }
        for (; j < end; j++) {
            int s0 = g_csr_src[j];
            float4 v0 = reinterpret_cast<const float4*>(g_z + (size_t)s0 * RS)[lane];
            acc.x += v0.x; acc.y += v0.y; acc.z += v0.z; acc.w += v0.w;
        }
        float4 zr = reinterpret_cast<const float4*>(g_z + (size_t)warp * RS + O)[lane];
        float4 bb = reinterpret_cast<const float4*>(b)[lane];
        float4 res;
        res.x = acc.x * inv + zr.x + bb.x;
        res.y = acc.y * inv + zr.y + bb.y;
        res.z = acc.z * inv + zr.z + bb.z;
        res.w = acc.w * inv + zr.w + bb.w;
        reinterpret_cast<float4*>(out + (size_t)warp * O)[lane] = res;
    } else {
        float2 acc = make_float2(0.f, 0.f);
        int j = beg;
        for (; j + 3 < end; j += 4) {
            int s0 = g_csr_src[j], s1 = g_csr_src[j + 1];
            int s2 = g_csr_src[j + 2], s3 = g_csr_src[j + 3];
            float2 v0 = reinterpret_cast<const float2*>(g_z + (size_t)s0 * RS)[lane];
            float2 v1 = reinterpret_cast<const float2*>(g_z + (size_t)s1 * RS)[lane];
            float2 v2 = reinterpret_cast<const float2*>(g_z + (size_t)s2 * RS)[lane];
            float2 v3 = reinterpret_cast<const float2*>(g_z + (size_t)s3 * RS)[lane];
            acc.x += (v0.x + v1.x) + (v2.x + v3.x);
            acc.y += (v0.y + v1.y) + (v2.y + v3.y);
        }
        for (; j < end; j++) {
            int s0 = g_csr_src[j];
            float2 v0 = reinterpret_cast<const float2*>(g_z + (size_t)s0 * RS)[lane];
            acc.x += v0.x; acc.y += v0.y;
        }
        float2 zr = reinterpret_cast<const float2*>(g_z + (size_t)warp * RS + O)[lane];
        float2 bb = reinterpret_cast<const float2*>(b)[lane];
        float2 res;
        res.x = acc.x * inv + zr.x + bb.x;
        res.y = acc.y * inv + zr.y + bb.y;
        reinterpret_cast<float2*>(out + (size_t)warp * O)[lane] = res;
    }
}

extern "C" void kernel_launch(void* const* d_in, const int* in_sizes, int n_in,
                              void* d_out, int out_size) {
    const float* x   = (const float*)d_in[0];
    const int*   ei  = (const int*)d_in[1];   // int32 (JAX x64 disabled)
    const float* Wl1 = (const float*)d_in[2];
    const float* b1  = (const float*)d_in[3];
    const float* Wr1 = (const float*)d_in[4];
    const float* Wl2 = (const float*)d_in[5];
    const float* b2  = (const float*)d_in[6];
    const float* Wr2 = (const float*)d_in[7];
    const float* Wl3 = (const float*)d_in[8];
    const float* b3  = (const float*)d_in[9];
    const float* Wr3 = (const float*)d_in[10];
    float* out = (float*)d_out;

    const int TB = 256;
    const int MT = (NNODES + 127) / 128;          // 391 M-tiles
    const int GW = (NNODES * 32 + TB - 1) / TB;   // gather: warp/node

    // CSR build
    zero_deg_kernel<<<(NNODES + TB - 1) / TB, TB>>>();
    count_kernel<<<(NEDGES + TB - 1) / TB, TB>>>(ei);
    scan_kernel<<<1, SCAN_T>>>();
    fill_kernel<<<(NEDGES + TB - 1) / TB, TB>>>(ei);

    // Layer 1: I=128, 2O=256
    gemm2_kernel<128, 256, 0><<<MT, 256>>>(x, Wl1, Wr1);
    gather_add_kernel<128, 1><<<GW, TB>>>(b1, nullptr);

    // Layer 2: I=128, 2O=128
    gemm2_kernel<128, 128, 1><<<MT, 128>>>(nullptr, Wl2, Wr2);
    gather_add_kernel<64, 2><<<GW, TB>>>(b2, nullptr);

    // Layer 3: I=64, 2O=256
    gemm2_kernel<64, 256, 2><<<MT, 256>>>(nullptr, Wl3, Wr3);
    gather_add_kernel<128, 0><<<GW, TB>>>(b3, out);
}